// round 15
// baseline (speedup 1.0000x reference)
#include <cuda_runtime.h>
#include <cstdint>

#define B_ 8
#define V_ 8192
#define N_ 2048
#define C_ 128
#define GRID_ 128
#define THR_ 640

typedef unsigned long long ull;

// ---------- f32x2 helpers (sm_100+ packed fp32) ----------
__device__ __forceinline__ ull pk2(float lo, float hi) {
    ull r; asm("mov.b64 %0, {%1, %2};" : "=l"(r) : "f"(lo), "f"(hi)); return r;
}
__device__ __forceinline__ void upk2(ull v, float& lo, float& hi) {
    asm("mov.b64 {%0, %1}, %2;" : "=f"(lo), "=f"(hi) : "l"(v));
}
__device__ __forceinline__ ull ffma2(ull a, ull b, ull c) {
    ull d; asm("fma.rn.f32x2 %0, %1, %2, %3;" : "=l"(d) : "l"(a), "l"(b), "l"(c)); return d;
}

// ---------- device scratch ----------
__device__ float g_buf[B_ * N_];
__device__ unsigned int bar1, bar_done;

// =====================================================================
// Persistent warp-specialized kernel. grid=128 (1 CTA/SM), 640 threads
// (20 warps = 5/SMSP, reg cap 102), 96KB dyn smem.
//   warps 0-3  : MLP. Tile R=8 rows x D=4 outputs (minimum-instruction
//                point: 2048 W-LDS + 4096 X-LDG per SM). 4 passes/warp.
//   warps 4-19 : screening. Q=8 verts x 256-pt slice (64 vg x 8 slices)
//                -> 4096 screen LDS per SM. Single running-min chain.
//   join -> partials to smem (dead W region) -> lex combine + exact
//   reference-rounding rescan (512 threads, 1 vertex each) ->
//   grid-barrier wait (hidden) -> gather.
// =====================================================================
__global__ void __launch_bounds__(THR_, 1)
kernelFused(const float* __restrict__ verts,
            const float* __restrict__ gpos,
            const float* __restrict__ processed,
            const float* __restrict__ W1,
            const float* __restrict__ b1,
            const float* __restrict__ W2,
            const float* __restrict__ b2,
            float* __restrict__ out) {
    extern __shared__ char sm[];
    ull*   Ws   = (ull*)sm;                   // 64KB packed W1 (split-half)
    float* cval = (float*)sm;                 // after join: 16 x 512 floats (32KB)
    int*   cseg = (int*)(sm + 32768);         // after join: 16 x 512 ints (32KB)
    float* pts  = (float*)(sm + 65536);       // 32KB pair-packed points
    __shared__ float red[128][33];

    const int t    = threadIdx.x;
    const int bid  = blockIdx.x;
    const int w    = t >> 5;
    const int lane = t & 31;

    const int vc = bid & 15;
    const int b  = bid >> 4;
    const int v0 = vc * 512;

    // ---------------- Cooperative setup ----------------
    // Pack W1 -> smem, split-half layout.
    for (int i = t; i < 8192; i += THR_) {
        int c2 = i >> 7;
        int r = i & 127;
        int d = 4 * ((r & 63) >> 1) + (r & 1) + ((r >> 6) << 1);
        Ws[i] = pk2(W1[(2 * c2) * C_ + d], W1[(2 * c2 + 1) * C_ + d]);
    }
    // Pair-packed point tile: pair j -> {x0,x1,y0,y1}{z0,z1,pp0,pp1}
    for (int j = t; j < N_ / 2; j += THR_) {
        const float* p0 = gpos + ((size_t)b * N_ + 2 * j) * 3;
        float x0 = p0[0], y0 = p0[1], z0 = p0[2];
        float x1 = p0[3], y1 = p0[4], z1 = p0[5];
        float pp0 = __fmaf_rn(z0, z0, __fmaf_rn(y0, y0, __fmul_rn(x0, x0)));
        float pp1 = __fmaf_rn(z1, z1, __fmaf_rn(y1, y1, __fmul_rn(x1, x1)));
        float4* d = (float4*)&pts[j * 8];
        d[0] = make_float4(x0, x1, y0, y1);
        d[1] = make_float4(z0, z1, pp0, pp1);
    }
    __syncthreads();

    const float INF = __int_as_float(0x7f800000);
    float best[8], sec[8];
    int sgpk[8];

    if (w < 4) {
        // ================= MLP group (threads 0..127) =================
        const int d0 = lane * 4;              // 4 outputs (split-half layout)
        float b1r[4], w2r[4];
#pragma unroll
        for (int j = 0; j < 4; j++) { b1r[j] = b1[d0 + j]; w2r[j] = W2[d0 + j]; }
        const ulonglong2* Wsv2 = (const ulonglong2*)Ws;
        const int rb = bid * 128;

        // 16 passes of 8 rows; warp w takes passes w, w+4, w+8, w+12
#pragma unroll 1
        for (int p = w; p < 16; p += 4) {
            const int r0 = p * 8;

            ull acc[8][4];
#pragma unroll
            for (int i = 0; i < 8; i++)
#pragma unroll
                for (int j = 0; j < 4; j++) acc[i][j] = 0ull;

#pragma unroll 2
            for (int c4 = 0; c4 < 32; c4++) {
                // W for both c2 halves: 4 LDS.128 (16B lane stride)
                ulonglong2 wa0 = Wsv2[(2 * c4) * 64 + lane];
                ulonglong2 wb0 = Wsv2[(2 * c4) * 64 + 32 + lane];
                ulonglong2 wa1 = Wsv2[(2 * c4 + 1) * 64 + lane];
                ulonglong2 wb1 = Wsv2[(2 * c4 + 1) * 64 + 32 + lane];
#pragma unroll
                for (int i = 0; i < 8; i++) {
                    // X: one uniform LDG.128 covers c2=2c4 and 2c4+1
                    ulonglong2 xv = *(const ulonglong2*)(processed +
                                     (size_t)(rb + r0 + i) * C_ + 4 * c4);
                    acc[i][0] = ffma2(xv.x, wa0.x, acc[i][0]);
                    acc[i][1] = ffma2(xv.x, wa0.y, acc[i][1]);
                    acc[i][2] = ffma2(xv.x, wb0.x, acc[i][2]);
                    acc[i][3] = ffma2(xv.x, wb0.y, acc[i][3]);
                    acc[i][0] = ffma2(xv.y, wa1.x, acc[i][0]);
                    acc[i][1] = ffma2(xv.y, wa1.y, acc[i][1]);
                    acc[i][2] = ffma2(xv.y, wb1.x, acc[i][2]);
                    acc[i][3] = ffma2(xv.y, wb1.y, acc[i][3]);
                }
            }

            // Epilogue: partial dot with W2 per row (same order as R14)
#pragma unroll
            for (int i = 0; i < 8; i++) {
                float part = 0.f;
#pragma unroll
                for (int j = 0; j < 4; j++) {
                    float lo, hi; upk2(acc[i][j], lo, hi);
                    float hv = fmaxf(lo + hi + b1r[j], 0.f);
                    part = fmaf(hv, w2r[j], part);
                }
                red[r0 + i][lane] = part;
            }
        }
        asm volatile("bar.sync 1, 128;" ::: "memory");
        if (t < 128) {
            float s = b2[0];
#pragma unroll
            for (int k = 0; k < 32; k++) s += red[t][k];
            g_buf[rb + t] = s;
        }
        asm volatile("bar.sync 1, 128;" ::: "memory");
        // Release g_buf: arrive on grid barrier (wait comes after join).
        if (t == 0) {
            __threadfence();
            atomicAdd(&bar1, 1u);
        }
    } else {
        // ================= Screen group (threads 128..639) =================
        const int ts = t - 128;               // 0..511
        const int ns = ts >> 6;               // 0..7: 256-pt slice (warp-const)
        const int vg = ts & 63;

        ull VX[8], VY[8], VZ[8];              // splatted -2*v : 48 regs
#pragma unroll
        for (int q = 0; q < 8; q++) {
            const float* vp = verts + ((size_t)b * V_ + v0 + vg + q * 64) * 3;
            float x = -2.f * vp[0], y = -2.f * vp[1], z = -2.f * vp[2];
            VX[q] = pk2(x, x); VY[q] = pk2(y, y); VZ[q] = pk2(z, z);
        }

#pragma unroll
        for (int q = 0; q < 8; q++) { best[q] = INF; sec[q] = INF; sgpk[q] = 0; }

        // 8 segments of 32 points (16 pairs) within this 256-pt slice
#pragma unroll 1
        for (int s = 0; s < 8; s++) {
            float m[8];
#pragma unroll
            for (int q = 0; q < 8; q++) m[q] = INF;
            const ulonglong2* base = (const ulonglong2*)&pts[(ns * 128 + s * 16) * 8];
#pragma unroll 4
            for (int k = 0; k < 16; k++) {
                ulonglong2 a  = base[2 * k];       // {x0,x1},{y0,y1}
                ulonglong2 bq = base[2 * k + 1];   // {z0,z1},{pp0,pp1}
#pragma unroll
                for (int q = 0; q < 8; q++) {
                    ull sc = ffma2(VZ[q], bq.x,
                              ffma2(VY[q], a.y,
                               ffma2(VX[q], a.x, bq.y)));
                    float lo, hi; upk2(sc, lo, hi);
                    m[q] = fminf(m[q], fminf(lo, hi));
                }
            }
#pragma unroll
            for (int q = 0; q < 8; q++) {
                int sp = sgpk[q];
                if (m[q] < best[q]) {
                    sec[q] = best[q]; sgpk[q] = ((sp & 0xff) << 8) | s;
                    best[q] = m[q];
                } else if (m[q] < sec[q]) {
                    sec[q] = m[q]; sgpk[q] = (sp & 0xff) | (s << 8);
                }
            }
        }
    }

    // ---------------- Join: W region retires ----------------
    __syncthreads();

    if (w >= 4) {
        const int ts = t - 128;
        const int ns = ts >> 6;
        const int vg = ts & 63;
#pragma unroll
        for (int q = 0; q < 8; q++) {
            int vloc = vg + q * 64;
            int gA = ns * 8 + (sgpk[q] & 0xff);    // global segment 0..63
            int gB = ns * 8 + (sgpk[q] >> 8);
            cval[(ns * 2 + 0) * 512 + vloc] = best[q];
            cseg[(ns * 2 + 0) * 512 + vloc] = gA;
            cval[(ns * 2 + 1) * 512 + vloc] = sec[q];
            cseg[(ns * 2 + 1) * 512 + vloc] = gB;
        }
    }
    __syncthreads();

    // ------------- Combine + exact rescan (threads t<512, 1 vertex) -------------
    int idx = 0;
    if (t < 512) {
        float bv = INF, sv = INF;
        int bs = 64, ss = 64;
#pragma unroll
        for (int e = 0; e < 16; e++) {
            float val = cval[e * 512 + t];
            int   sg  = cseg[e * 512 + t];
            bool better = (val < bv) || (val == bv && sg < bs);
            if (better) {
                sv = bv; ss = bs; bv = val; bs = sg;
            } else if ((val < sv) || (val == sv && sg < ss)) {
                sv = val; ss = sg;
            }
        }

        const float* vp = verts + ((size_t)b * V_ + v0 + t) * 3;
        float vx = vp[0], vy = vp[1], vz = vp[2];
        float nvx = -2.f * vx, nvy = -2.f * vy, nvz = -2.f * vz;
        float vv = __fmaf_rn(vz, vz, __fmaf_rn(vy, vy, __fmul_rn(vx, vx)));

        int lo = min(bs, ss);
        int hi = max(bs, ss);
        float cur = INF;
#pragma unroll 1
        for (int pass = 0; pass < 2; pass++) {
            if (pass == 1 && hi == lo) break;
            int sb = (pass == 0 ? lo : hi) * 32;
            const ulonglong2* basep = (const ulonglong2*)&pts[(sb >> 1) * 8];
#pragma unroll 1
            for (int j = 0; j < 16; j++) {
                ulonglong2 A  = basep[2 * j];
                ulonglong2 Bq = basep[2 * j + 1];
                float x0, x1, y0, y1, z0, z1, w0, w1;
                upk2(A.x, x0, x1); upk2(A.y, y0, y1);
                upk2(Bq.x, z0, z1); upk2(Bq.y, w0, w1);
                float s2 = __fmaf_rn(nvz, z0, __fmaf_rn(nvy, y0, __fmul_rn(nvx, x0)));
                float d2 = __fadd_rn(__fadd_rn(vv, s2), w0);
                if (d2 < cur) { cur = d2; idx = sb + 2 * j; }
                float s3 = __fmaf_rn(nvz, z1, __fmaf_rn(nvy, y1, __fmul_rn(nvx, x1)));
                float d3 = __fadd_rn(__fadd_rn(vv, s3), w1);
                if (d3 < cur) { cur = d3; idx = sb + 2 * j + 1; }
            }
        }
    }

    // ---- Grid barrier WAIT (arrive happened long ago; mostly hidden) ----
    if (t == 0) {
        while (*(volatile unsigned int*)&bar1 < GRID_) __nanosleep(64);
    }
    __syncthreads();
    __threadfence();

    // ---- Gather ----
    if (t < 512) out[b * V_ + v0 + t] = g_buf[b * N_ + idx];

    // ---------------- Exit: reset barrier (last block) ----------------
    __syncthreads();
    if (t == 0) {
        unsigned int r = atomicAdd(&bar_done, 1u);
        if (r == GRID_ - 1) {
            atomicExch(&bar1, 0u);
            atomicExch(&bar_done, 0u);
        }
    }
}

// =====================================================================
extern "C" void kernel_launch(void* const* d_in, const int* in_sizes, int n_in,
                              void* d_out, int out_size) {
    const float* verts = (const float*)d_in[0];   // [8,8192,3]
    const float* gpos  = (const float*)d_in[1];   // [8,2048,3]
    const float* proc  = (const float*)d_in[2];   // [8,2048,128]
    const float* W1    = (const float*)d_in[3];   // [128,128]
    const float* b1    = (const float*)d_in[4];   // [128]
    const float* W2    = (const float*)d_in[5];   // [128,1]
    const float* b2    = (const float*)d_in[6];   // [1]
    float* out = (float*)d_out;                   // [8,8192,1]

    cudaFuncSetAttribute(kernelFused, cudaFuncAttributeMaxDynamicSharedMemorySize,
                         96 * 1024);
    kernelFused<<<GRID_, THR_, 96 * 1024>>>(verts, gpos, proc, W1, b1, W2, b2, out);
}

// round 16
// speedup vs baseline: 1.6209x; 1.6209x over previous
#include <cuda_runtime.h>
#include <cstdint>

#define B_ 8
#define V_ 8192
#define N_ 2048
#define C_ 128
#define GRID_ 128
#define THR_ 512

typedef unsigned long long ull;

// ---------- f32x2 helpers (sm_100+ packed fp32) ----------
__device__ __forceinline__ ull pk2(float lo, float hi) {
    ull r; asm("mov.b64 %0, {%1, %2};" : "=l"(r) : "f"(lo), "f"(hi)); return r;
}
__device__ __forceinline__ void upk2(ull v, float& lo, float& hi) {
    asm("mov.b64 {%0, %1}, %2;" : "=f"(lo), "=f"(hi) : "l"(v));
}
__device__ __forceinline__ ull ffma2(ull a, ull b, ull c) {
    ull d; asm("fma.rn.f32x2 %0, %1, %2, %3;" : "=l"(d) : "l"(a), "l"(b), "l"(c)); return d;
}

// ---------- device scratch ----------
__device__ float g_buf[B_ * N_];
__device__ unsigned int bar1, bar_done;

// =====================================================================
// Persistent warp-specialized kernel (R13 shape + wavefront halvings).
// grid=128 (1 CTA/SM), 512 threads, 96KB dyn smem.
//   warps 0-7  : MLP (256 thr). 8-row tiles (acc[8][4]) with BATCHED
//                xv[8] uniform-LDG prefetch (MLP preserved!). W smem
//                re-read per 8 rows -> W wavefronts halved vs R13.
//   warps 8-15 : screening (256 thr). Q=8 verts x 512-pt slice ->
//                screen LDS halved vs R13. Best-2 segs in registers.
//   join -> partials to smem (dead W region) -> lex combine + exact
//   reference-rounding rescan (all 512 thr, 1 vertex each) ->
//   grid-barrier wait (hidden) -> gather.
// =====================================================================
__global__ void __launch_bounds__(THR_, 1)
kernelFused(const float* __restrict__ verts,
            const float* __restrict__ gpos,
            const float* __restrict__ processed,
            const float* __restrict__ W1,
            const float* __restrict__ b1,
            const float* __restrict__ W2,
            const float* __restrict__ b2,
            float* __restrict__ out) {
    extern __shared__ char sm[];
    ull*   Ws   = (ull*)sm;                   // 64KB packed W1 (split-half)
    float* cval = (float*)sm;                 // after join: 8 x 512 floats (16KB)
    int*   cseg = (int*)(sm + 16384);         // after join: 8 x 512 ints (16KB)
    float* pts  = (float*)(sm + 65536);       // 32KB pair-packed points
    __shared__ float red[128][33];

    const int t    = threadIdx.x;
    const int bid  = blockIdx.x;
    const int w    = t >> 5;
    const int lane = t & 31;

    const int vc = bid & 15;
    const int b  = bid >> 4;
    const int v0 = vc * 512;

    // ---------------- Cooperative setup ----------------
    // Pack W1 -> smem, split-half layout.
#pragma unroll
    for (int k = 0; k < 16; k++) {
        int i = t + k * THR_;                 // 0..8191
        int c2 = i >> 7;
        int r = i & 127;
        int d = 4 * ((r & 63) >> 1) + (r & 1) + ((r >> 6) << 1);
        Ws[i] = pk2(W1[(2 * c2) * C_ + d], W1[(2 * c2 + 1) * C_ + d]);
    }
    // Pair-packed point tile: pair j -> {x0,x1,y0,y1}{z0,z1,pp0,pp1}
#pragma unroll
    for (int k = 0; k < 2; k++) {
        int j = t + k * THR_;                 // 0..1023
        const float* p0 = gpos + ((size_t)b * N_ + 2 * j) * 3;
        float x0 = p0[0], y0 = p0[1], z0 = p0[2];
        float x1 = p0[3], y1 = p0[4], z1 = p0[5];
        float pp0 = __fmaf_rn(z0, z0, __fmaf_rn(y0, y0, __fmul_rn(x0, x0)));
        float pp1 = __fmaf_rn(z1, z1, __fmaf_rn(y1, y1, __fmul_rn(x1, x1)));
        float4* d = (float4*)&pts[j * 8];
        d[0] = make_float4(x0, x1, y0, y1);
        d[1] = make_float4(z0, z1, pp0, pp1);
    }
    __syncthreads();

    const float INF = __int_as_float(0x7f800000);
    float best[8], sec[8];
    int sgpk[8];

    if (w < 8) {
        // ================= MLP group (threads 0..255) =================
        const int d0 = lane * 4;              // 4 outputs (split-half layout)
        float b1r[4], w2r[4];
#pragma unroll
        for (int j = 0; j < 4; j++) { b1r[j] = b1[d0 + j]; w2r[j] = W2[d0 + j]; }
        const ulonglong2* Wsv2 = (const ulonglong2*)Ws;
        const int rb = bid * 128;

        // 16 groups of 8 rows; warp w takes groups w and w+8.
#pragma unroll 1
        for (int p = w; p < 16; p += 8) {
            const int r0 = p * 8;

            ull acc[8][4];
#pragma unroll
            for (int i = 0; i < 8; i++)
#pragma unroll
                for (int j = 0; j < 4; j++) acc[i][j] = 0ull;

#pragma unroll 2
            for (int c4 = 0; c4 < 32; c4++) {
                // BATCHED X prefetch: 8 uniform LDG.128 (MLP = 8)
                ulonglong2 xv[8];
#pragma unroll
                for (int i = 0; i < 8; i++)
                    xv[i] = *(const ulonglong2*)(processed +
                             (size_t)(rb + r0 + i) * C_ + 4 * c4);
#pragma unroll
                for (int half = 0; half < 2; half++) {
                    const int c2 = 2 * c4 + half;
                    ulonglong2 wa = Wsv2[c2 * 64 + lane];        // d = 4l,4l+1
                    ulonglong2 wb = Wsv2[c2 * 64 + 32 + lane];   // d = 4l+2,4l+3
                    ull w2v[4] = {wa.x, wa.y, wb.x, wb.y};
#pragma unroll
                    for (int i = 0; i < 8; i++) {
                        ull xi = half ? xv[i].y : xv[i].x;
#pragma unroll
                        for (int j = 0; j < 4; j++)
                            acc[i][j] = ffma2(xi, w2v[j], acc[i][j]);
                    }
                }
            }

            // Epilogue: partial dot with W2 per row
#pragma unroll
            for (int i = 0; i < 8; i++) {
                float part = 0.f;
#pragma unroll
                for (int j = 0; j < 4; j++) {
                    float lo, hi; upk2(acc[i][j], lo, hi);
                    float hv = fmaxf(lo + hi + b1r[j], 0.f);
                    part = fmaf(hv, w2r[j], part);
                }
                red[r0 + i][lane] = part;
            }
        }
        asm volatile("bar.sync 1, 256;" ::: "memory");
        if (t < 128) {
            float s = b2[0];
#pragma unroll
            for (int k = 0; k < 32; k++) s += red[t][k];
            g_buf[rb + t] = s;
        }
        asm volatile("bar.sync 1, 256;" ::: "memory");
        // Release g_buf: arrive on grid barrier (wait comes after join).
        if (t == 0) {
            __threadfence();
            atomicAdd(&bar1, 1u);
        }
    } else {
        // ================= Screen group (threads 256..511) =================
        const int ts = t - 256;               // 0..255
        const int ns = ts >> 6;               // 0..3: 512-pt slice (warp-const)
        const int vg = ts & 63;

        ull VX[8], VY[8], VZ[8];              // splatted -2*v : 48 regs
#pragma unroll
        for (int q = 0; q < 8; q++) {
            const float* vp = verts + ((size_t)b * V_ + v0 + vg + q * 64) * 3;
            float x = -2.f * vp[0], y = -2.f * vp[1], z = -2.f * vp[2];
            VX[q] = pk2(x, x); VY[q] = pk2(y, y); VZ[q] = pk2(z, z);
        }

#pragma unroll
        for (int q = 0; q < 8; q++) { best[q] = INF; sec[q] = INF; sgpk[q] = 0; }

        // 16 segments of 32 points (16 pairs) within this 512-pt slice
#pragma unroll 1
        for (int s = 0; s < 16; s++) {
            float m[8];
#pragma unroll
            for (int q = 0; q < 8; q++) m[q] = INF;
            const ulonglong2* base = (const ulonglong2*)&pts[(ns * 256 + s * 16) * 8];
#pragma unroll 4
            for (int k = 0; k < 16; k++) {
                ulonglong2 a  = base[2 * k];       // {x0,x1},{y0,y1}
                ulonglong2 bq = base[2 * k + 1];   // {z0,z1},{pp0,pp1}
#pragma unroll
                for (int q = 0; q < 8; q++) {
                    ull sc = ffma2(VZ[q], bq.x,
                              ffma2(VY[q], a.y,
                               ffma2(VX[q], a.x, bq.y)));
                    float lo, hi; upk2(sc, lo, hi);
                    m[q] = fminf(m[q], fminf(lo, hi));
                }
            }
#pragma unroll
            for (int q = 0; q < 8; q++) {
                int sp = sgpk[q];
                if (m[q] < best[q]) {
                    sec[q] = best[q]; sgpk[q] = ((sp & 0xff) << 8) | s;
                    best[q] = m[q];
                } else if (m[q] < sec[q]) {
                    sec[q] = m[q]; sgpk[q] = (sp & 0xff) | (s << 8);
                }
            }
        }
    }

    // ---------------- Join: W region retires ----------------
    __syncthreads();

    if (w >= 8) {
        const int ts = t - 256;
        const int ns = ts >> 6;
        const int vg = ts & 63;
#pragma unroll
        for (int q = 0; q < 8; q++) {
            int vloc = vg + q * 64;
            int gA = ns * 16 + (sgpk[q] & 0xff);   // global segment 0..63
            int gB = ns * 16 + (sgpk[q] >> 8);
            cval[(ns * 2 + 0) * 512 + vloc] = best[q];
            cseg[(ns * 2 + 0) * 512 + vloc] = gA;
            cval[(ns * 2 + 1) * 512 + vloc] = sec[q];
            cseg[(ns * 2 + 1) * 512 + vloc] = gB;
        }
    }
    __syncthreads();

    // ------------- Combine + exact rescan (all 512 thr, 1 vertex) -------------
    int idx = 0;
    {
        float bv = INF, sv = INF;
        int bs = 64, ss = 64;
#pragma unroll
        for (int e = 0; e < 8; e++) {
            float val = cval[e * 512 + t];
            int   sg  = cseg[e * 512 + t];
            bool better = (val < bv) || (val == bv && sg < bs);
            if (better) {
                sv = bv; ss = bs; bv = val; bs = sg;
            } else if ((val < sv) || (val == sv && sg < ss)) {
                sv = val; ss = sg;
            }
        }

        const float* vp = verts + ((size_t)b * V_ + v0 + t) * 3;
        float vx = vp[0], vy = vp[1], vz = vp[2];
        float nvx = -2.f * vx, nvy = -2.f * vy, nvz = -2.f * vz;
        float vv = __fmaf_rn(vz, vz, __fmaf_rn(vy, vy, __fmul_rn(vx, vx)));

        int lo = min(bs, ss);
        int hi = max(bs, ss);
        float cur = INF;
#pragma unroll 1
        for (int pass = 0; pass < 2; pass++) {
            if (pass == 1 && hi == lo) break;
            int sb = (pass == 0 ? lo : hi) * 32;
            const ulonglong2* basep = (const ulonglong2*)&pts[(sb >> 1) * 8];
#pragma unroll 1
            for (int j = 0; j < 16; j++) {
                ulonglong2 A  = basep[2 * j];
                ulonglong2 Bq = basep[2 * j + 1];
                float x0, x1, y0, y1, z0, z1, w0, w1;
                upk2(A.x, x0, x1); upk2(A.y, y0, y1);
                upk2(Bq.x, z0, z1); upk2(Bq.y, w0, w1);
                float s2 = __fmaf_rn(nvz, z0, __fmaf_rn(nvy, y0, __fmul_rn(nvx, x0)));
                float d2 = __fadd_rn(__fadd_rn(vv, s2), w0);
                if (d2 < cur) { cur = d2; idx = sb + 2 * j; }
                float s3 = __fmaf_rn(nvz, z1, __fmaf_rn(nvy, y1, __fmul_rn(nvx, x1)));
                float d3 = __fadd_rn(__fadd_rn(vv, s3), w1);
                if (d3 < cur) { cur = d3; idx = sb + 2 * j + 1; }
            }
        }
    }

    // ---- Grid barrier WAIT (arrive happened long ago; mostly hidden) ----
    if (t == 0) {
        while (*(volatile unsigned int*)&bar1 < GRID_) __nanosleep(64);
    }
    __syncthreads();
    __threadfence();

    // ---- Gather ----
    out[b * V_ + v0 + t] = g_buf[b * N_ + idx];

    // ---------------- Exit: reset barrier (last block) ----------------
    __syncthreads();
    if (t == 0) {
        unsigned int r = atomicAdd(&bar_done, 1u);
        if (r == GRID_ - 1) {
            atomicExch(&bar1, 0u);
            atomicExch(&bar_done, 0u);
        }
    }
}

// =====================================================================
extern "C" void kernel_launch(void* const* d_in, const int* in_sizes, int n_in,
                              void* d_out, int out_size) {
    const float* verts = (const float*)d_in[0];   // [8,8192,3]
    const float* gpos  = (const float*)d_in[1];   // [8,2048,3]
    const float* proc  = (const float*)d_in[2];   // [8,2048,128]
    const float* W1    = (const float*)d_in[3];   // [128,128]
    const float* b1    = (const float*)d_in[4];   // [128]
    const float* W2    = (const float*)d_in[5];   // [128,1]
    const float* b2    = (const float*)d_in[6];   // [1]
    float* out = (float*)d_out;                   // [8,8192,1]

    cudaFuncSetAttribute(kernelFused, cudaFuncAttributeMaxDynamicSharedMemorySize,
                         96 * 1024);
    kernelFused<<<GRID_, THR_, 96 * 1024>>>(verts, gpos, proc, W1, b1, W2, b2, out);
}